// round 2
// baseline (speedup 1.0000x reference)
#include <cuda_runtime.h>
#include <cuda_bf16.h>

// Problem constants (fixed by the reference)
#define NTOT   2048          // nodes total (32 graphs * 64 nodes)
#define NGR    32            // graphs
#define NPG    64            // nodes per graph
#define C      384           // in/emb/out channels
#define G12    12            // tetra group size
#define HEFF   2             // heads per group
#define GH     24            // G12*HEFF
#define HD     16            // head dim

// Scratch (device globals — no allocation allowed)
__device__ float g_q[NTOT * C];
__device__ float g_k[NTOT * C];
__device__ float g_v[NTOT * C];
__device__ float g_a[NTOT * C];

// ---------------------------------------------------------------------------
// Generic tiled SGEMM: C[M,N] = A[M,K] @ B[K,N] + bias[N]
// BM=64, BN=64, BK=16, 256 threads, 4x4 micro-tile per thread.
// All dims here are multiples of the tile sizes (2048, 384, 384) -> no guards.
// ---------------------------------------------------------------------------
__global__ __launch_bounds__(256) void gemm_bias_kernel(
    const float* __restrict__ A, const float* __restrict__ B,
    const float* __restrict__ bias, float* __restrict__ Cout,
    int M, int N, int K)
{
    __shared__ float As[16][64];   // transposed A tile: As[k][m]
    __shared__ float Bs[16][64];   // Bs[k][n]

    const int tid = threadIdx.x;
    const int tx = tid & 15;       // 16 cols of threads
    const int ty = tid >> 4;       // 16 rows of threads
    const int br = blockIdx.y;     // row tile
    const int bc = blockIdx.x;     // col tile

    float acc[4][4] = {};

    for (int kt = 0; kt < K; kt += 16) {
        // Load A tile 64x16 (row-major global) -> As transposed
        #pragma unroll
        for (int l = 0; l < 4; l++) {
            int idx = tid + l * 256;          // 0..1023
            int r = idx >> 4, c = idx & 15;   // r: 0..63, c: 0..15
            As[c][r] = A[(br * 64 + r) * K + kt + c];
        }
        // Load B tile 16x64
        #pragma unroll
        for (int l = 0; l < 4; l++) {
            int idx = tid + l * 256;
            int r = idx >> 6, c = idx & 63;   // r: 0..15, c: 0..63
            Bs[r][c] = B[(kt + r) * N + bc * 64 + c];
        }
        __syncthreads();

        #pragma unroll
        for (int k = 0; k < 16; k++) {
            float ra[4], rb[4];
            #pragma unroll
            for (int i = 0; i < 4; i++) ra[i] = As[k][ty * 4 + i];
            #pragma unroll
            for (int j = 0; j < 4; j++) rb[j] = Bs[k][tx * 4 + j];
            #pragma unroll
            for (int i = 0; i < 4; i++)
                #pragma unroll
                for (int j = 0; j < 4; j++)
                    acc[i][j] = fmaf(ra[i], rb[j], acc[i][j]);
        }
        __syncthreads();
    }

    #pragma unroll
    for (int i = 0; i < 4; i++) {
        int row = br * 64 + ty * 4 + i;
        #pragma unroll
        for (int j = 0; j < 4; j++) {
            int col = bc * 64 + tx * 4 + j;
            Cout[row * N + col] = acc[i][j] + bias[col];
        }
    }
}

// ---------------------------------------------------------------------------
// RoPE: theta[n,h,f] = sum_s pos[n,s] * freqs[s,h,f]; rotate pairs (2f,2f+1)
// of q and k across all 12 group copies.
// One thread per (n,h,f): NTOT*HEFF*8 = 32768 threads, 12-group inner loop.
// ---------------------------------------------------------------------------
__global__ void rope_kernel(const float* __restrict__ pos,
                            const float* __restrict__ freqs)
{
    int tid = blockIdx.x * blockDim.x + threadIdx.x;
    if (tid >= NTOT * HEFF * (HD / 2)) return;
    int f = tid & 7;
    int h = (tid >> 3) & 1;
    int n = tid >> 4;

    // freqs layout [3, HEFF, HD/2] = [3,2,8]
    float th = pos[n * 3 + 0] * freqs[0 * 16 + h * 8 + f]
             + pos[n * 3 + 1] * freqs[1 * 16 + h * 8 + f]
             + pos[n * 3 + 2] * freqs[2 * 16 + h * 8 + f];
    float s, c;
    __sincosf(th, &s, &c);

    int base = n * C + h * HD + 2 * f;
    #pragma unroll
    for (int g = 0; g < G12; g++) {
        int idx = base + g * (HEFF * HD);   // g*32
        float q1 = g_q[idx], q2 = g_q[idx + 1];
        g_q[idx]     = q1 * c - q2 * s;
        g_q[idx + 1] = q1 * s + q2 * c;
        float k1 = g_k[idx], k2 = g_k[idx + 1];
        g_k[idx]     = k1 * c - k2 * s;
        g_k[idx + 1] = k1 * s + k2 * c;
    }
}

// ---------------------------------------------------------------------------
// Dense attention per (graph, group-head): 64x64 scores, softmax over keys,
// O = softmax(QK^T/4) @ V. Block = 64 threads (one query row per thread).
// ---------------------------------------------------------------------------
__global__ __launch_bounds__(64) void attn_kernel()
{
    const int gh    = blockIdx.x;   // 0..23
    const int graph = blockIdx.y;   // 0..31
    const int i     = threadIdx.x;  // query row 0..63

    __shared__ float Ks[64][16];
    __shared__ float Vs[64][16];
    __shared__ float S[64][65];     // padded to kill bank conflicts

    const int node = graph * NPG + i;
    const int off  = node * C + gh * HD;

    // Load my K/V row into shared, my Q row into registers (float4 vectorized)
    float qr[16];
    {
        const float4* qp = reinterpret_cast<const float4*>(g_q + off);
        const float4* kp = reinterpret_cast<const float4*>(g_k + off);
        const float4* vp = reinterpret_cast<const float4*>(g_v + off);
        float4* ks = reinterpret_cast<float4*>(&Ks[i][0]);
        float4* vs = reinterpret_cast<float4*>(&Vs[i][0]);
        #pragma unroll
        for (int t = 0; t < 4; t++) {
            float4 qv = qp[t];
            qr[t*4+0] = qv.x; qr[t*4+1] = qv.y; qr[t*4+2] = qv.z; qr[t*4+3] = qv.w;
            ks[t] = kp[t];
            vs[t] = vp[t];
        }
    }
    __syncthreads();

    // Scores + running max
    float m = -1e30f;
    #pragma unroll 4
    for (int j = 0; j < 64; j++) {
        float s = 0.f;
        #pragma unroll
        for (int d = 0; d < 16; d++) s = fmaf(qr[d], Ks[j][d], s);
        s *= 0.25f;                 // HEAD_D^-0.5 = 1/4
        S[i][j] = s;
        m = fmaxf(m, s);
    }

    // exp, denominator, weighted V accumulation
    float den = 0.f;
    float o[16] = {};
    #pragma unroll 4
    for (int j = 0; j < 64; j++) {
        float e = __expf(S[i][j] - m);
        den += e;
        #pragma unroll
        for (int d = 0; d < 16; d++) o[d] = fmaf(e, Vs[j][d], o[d]);
    }
    float inv = 1.f / den;
    #pragma unroll
    for (int d = 0; d < 16; d++) g_a[off + d] = o[d] * inv;
}

// ---------------------------------------------------------------------------
extern "C" void kernel_launch(void* const* d_in, const int* in_sizes, int n_in,
                              void* d_out, int out_size)
{
    const float* x     = (const float*)d_in[0];
    const float* pos   = (const float*)d_in[1];
    const float* Wq    = (const float*)d_in[2];
    const float* bq    = (const float*)d_in[3];
    const float* Wk    = (const float*)d_in[4];
    const float* bk    = (const float*)d_in[5];
    const float* Wv    = (const float*)d_in[6];
    const float* bv    = (const float*)d_in[7];
    const float* Wo    = (const float*)d_in[8];
    const float* bo    = (const float*)d_in[9];
    const float* rfreq = (const float*)d_in[10];
    // d_in[11] = src, d_in[12] = dst : fully-connected within graph -> implicit
    float* out = (float*)d_out;

    float *qp, *kp, *vp, *ap;
    cudaGetSymbolAddress((void**)&qp, g_q);
    cudaGetSymbolAddress((void**)&kp, g_k);
    cudaGetSymbolAddress((void**)&vp, g_v);
    cudaGetSymbolAddress((void**)&ap, g_a);

    dim3 ggrid(C / 64, NTOT / 64);   // (6, 32)

    gemm_bias_kernel<<<ggrid, 256>>>(x, Wq, bq, qp, NTOT, C, C);
    gemm_bias_kernel<<<ggrid, 256>>>(x, Wk, bk, kp, NTOT, C, C);
    gemm_bias_kernel<<<ggrid, 256>>>(x, Wv, bv, vp, NTOT, C, C);

    rope_kernel<<<(NTOT * 16 + 255) / 256, 256>>>(pos, rfreq);

    attn_kernel<<<dim3(GH, NGR), 64>>>();

    gemm_bias_kernel<<<ggrid, 256>>>(ap, Wo, bo, out, NTOT, C, C);
}

// round 3
// speedup vs baseline: 1.2967x; 1.2967x over previous
#include <cuda_runtime.h>
#include <cuda_bf16.h>
#include <mma.h>

using namespace nvcuda;

// Problem constants (fixed by the reference)
#define NTOT   2048          // nodes total (32 graphs * 64 nodes)
#define NGR    32            // graphs
#define NPG    64            // nodes per graph
#define C      384           // in/emb/out channels
#define G12    12            // tetra group size
#define HEFF   2             // heads per group
#define GH     24            // G12*HEFF
#define HD     16            // head dim

// Scratch (device globals — no allocation allowed)
__device__ float g_q[NTOT * C];
__device__ float g_k[NTOT * C];
__device__ float g_v[NTOT * C];
__device__ float g_a[NTOT * C];

// ---------------------------------------------------------------------------
// Tensor-core GEMM, 3xTF32 (fp32-accurate): C[M,N] = A[M,K] @ B[K,N] + bias.
// 64x64 tile, BK=16, 128 threads = 4 warps, each warp owns a 32x32 quadrant
// (2x2 wmma 16x16x8 tiles). Handles up to 3 different B/bias/out per launch
// selected by blockIdx.x (used to fuse the Q,K,V projections).
// Dims are multiples of tile sizes (2048 x 384 x 384) -> no guards.
// ---------------------------------------------------------------------------
__global__ __launch_bounds__(128) void gemm3_tf32_kernel(
    const float* __restrict__ A,
    const float* __restrict__ B0, const float* __restrict__ B1, const float* __restrict__ B2,
    const float* __restrict__ bias0, const float* __restrict__ bias1, const float* __restrict__ bias2,
    float* __restrict__ O0, float* __restrict__ O1, float* __restrict__ O2,
    int K, int N)
{
    const int ntiles = N >> 6;
    const int which = blockIdx.x / ntiles;
    const int bc    = blockIdx.x % ntiles;
    const int br    = blockIdx.y;

    const float* B    = (which == 0) ? B0    : (which == 1) ? B1    : B2;
    const float* bias = (which == 0) ? bias0 : (which == 1) ? bias1 : bias2;
    float*       O    = (which == 0) ? O0    : (which == 1) ? O1    : O2;

    __shared__ float As[2][64][16];   // [hi/lo][m][k]
    __shared__ float Bs[2][16][64];   // [hi/lo][k][n]
    __shared__ float Cs[64][64];

    const int tid  = threadIdx.x;
    const int warp = tid >> 5;
    const int wr   = warp >> 1;       // warp row quadrant (0/1)
    const int wc   = warp & 1;        // warp col quadrant (0/1)

    wmma::fragment<wmma::accumulator, 16, 16, 8, float> acc[2][2];
    #pragma unroll
    for (int i = 0; i < 2; i++)
        #pragma unroll
        for (int j = 0; j < 2; j++)
            wmma::fill_fragment(acc[i][j], 0.0f);

    for (int kt = 0; kt < K; kt += 16) {
        // Load A tile 64x16, split into tf32 hi + lo
        #pragma unroll
        for (int l = 0; l < 8; l++) {
            int idx = tid + l * 128;            // 0..1023
            int r = idx >> 4, c = idx & 15;
            float a  = A[(br * 64 + r) * K + kt + c];
            float hi = wmma::__float_to_tf32(a);
            As[0][r][c] = hi;
            As[1][r][c] = wmma::__float_to_tf32(a - hi);
        }
        // Load B tile 16x64, split into tf32 hi + lo
        #pragma unroll
        for (int l = 0; l < 8; l++) {
            int idx = tid + l * 128;
            int r = idx >> 6, c = idx & 63;
            float b  = B[(kt + r) * N + bc * 64 + c];
            float hi = wmma::__float_to_tf32(b);
            Bs[0][r][c] = hi;
            Bs[1][r][c] = wmma::__float_to_tf32(b - hi);
        }
        __syncthreads();

        #pragma unroll
        for (int ks = 0; ks < 2; ks++) {
            wmma::fragment<wmma::matrix_a, 16, 16, 8, wmma::precision::tf32, wmma::row_major> ah[2], al[2];
            wmma::fragment<wmma::matrix_b, 16, 16, 8, wmma::precision::tf32, wmma::row_major> bh[2], bl[2];
            #pragma unroll
            for (int i = 0; i < 2; i++) {
                wmma::load_matrix_sync(ah[i], &As[0][wr * 32 + i * 16][ks * 8], 16);
                wmma::load_matrix_sync(al[i], &As[1][wr * 32 + i * 16][ks * 8], 16);
            }
            #pragma unroll
            for (int j = 0; j < 2; j++) {
                wmma::load_matrix_sync(bh[j], &Bs[0][ks * 8][wc * 32 + j * 16], 64);
                wmma::load_matrix_sync(bl[j], &Bs[1][ks * 8][wc * 32 + j * 16], 64);
            }
            #pragma unroll
            for (int i = 0; i < 2; i++)
                #pragma unroll
                for (int j = 0; j < 2; j++) {
                    wmma::mma_sync(acc[i][j], ah[i], bh[j], acc[i][j]);
                    wmma::mma_sync(acc[i][j], ah[i], bl[j], acc[i][j]);
                    wmma::mma_sync(acc[i][j], al[i], bh[j], acc[i][j]);
                }
        }
        __syncthreads();
    }

    // Epilogue: accumulators -> smem -> global (+bias), fully coalesced
    #pragma unroll
    for (int i = 0; i < 2; i++)
        #pragma unroll
        for (int j = 0; j < 2; j++)
            wmma::store_matrix_sync(&Cs[wr * 32 + i * 16][wc * 32 + j * 16],
                                    acc[i][j], 64, wmma::mem_row_major);
    __syncthreads();

    #pragma unroll
    for (int l = 0; l < 32; l++) {
        int idx = tid + l * 128;                // 0..4095
        int r = idx >> 6, c = idx & 63;
        O[(br * 64 + r) * N + bc * 64 + c] = Cs[r][c] + bias[bc * 64 + c];
    }
}

// ---------------------------------------------------------------------------
// Dense attention per (graph, group-head) with RoPE fused into the load phase.
// theta[n,h,f] = sum_s pos[n,s] * freqs[s,h,f]; rotate q,k pairs, then
// O = softmax(QK^T / 4) @ V over the 64 nodes of the graph.
// Block = 64 threads (one query row per thread).
// ---------------------------------------------------------------------------
__global__ __launch_bounds__(64) void attn_kernel(const float* __restrict__ pos,
                                                  const float* __restrict__ freqs)
{
    const int gh    = blockIdx.x;   // 0..23 (= g*HEFF + h)
    const int graph = blockIdx.y;   // 0..31
    const int i     = threadIdx.x;  // query/key row 0..63
    const int h     = gh & 1;       // head-within-group

    __shared__ float Ks[64][16];
    __shared__ float Vs[64][16];
    __shared__ float S[64][65];     // padded to kill bank conflicts

    const int node = graph * NPG + i;
    const int off  = node * C + gh * HD;

    // Load q,k rows into registers; v row into shared (float4 vectorized)
    float qr[16], kr[16];
    {
        const float4* qp = reinterpret_cast<const float4*>(g_q + off);
        const float4* kp = reinterpret_cast<const float4*>(g_k + off);
        const float4* vp = reinterpret_cast<const float4*>(g_v + off);
        float4* vs = reinterpret_cast<float4*>(&Vs[i][0]);
        #pragma unroll
        for (int t = 0; t < 4; t++) {
            float4 qv = qp[t];
            qr[4*t+0] = qv.x; qr[4*t+1] = qv.y; qr[4*t+2] = qv.z; qr[4*t+3] = qv.w;
            float4 kv = kp[t];
            kr[4*t+0] = kv.x; kr[4*t+1] = kv.y; kr[4*t+2] = kv.z; kr[4*t+3] = kv.w;
            vs[t] = vp[t];
        }
    }

    // Fused RoPE: rotate (2f, 2f+1) pairs of q and k
    const float p0 = pos[node * 3 + 0];
    const float p1 = pos[node * 3 + 1];
    const float p2 = pos[node * 3 + 2];
    #pragma unroll
    for (int f = 0; f < 8; f++) {
        // freqs layout [3, HEFF, HD/2] = [3, 2, 8]
        float th = p0 * freqs[ 0 + h * 8 + f]
                 + p1 * freqs[16 + h * 8 + f]
                 + p2 * freqs[32 + h * 8 + f];
        float s, c;
        __sincosf(th, &s, &c);
        float q1 = qr[2*f], q2 = qr[2*f+1];
        qr[2*f]   = q1 * c - q2 * s;
        qr[2*f+1] = q1 * s + q2 * c;
        float k1 = kr[2*f], k2 = kr[2*f+1];
        kr[2*f]   = k1 * c - k2 * s;
        kr[2*f+1] = k1 * s + k2 * c;
    }
    #pragma unroll
    for (int d = 0; d < 16; d++) Ks[i][d] = kr[d];
    __syncthreads();

    // Scores + running max
    float m = -1e30f;
    #pragma unroll 4
    for (int j = 0; j < 64; j++) {
        float s = 0.f;
        #pragma unroll
        for (int d = 0; d < 16; d++) s = fmaf(qr[d], Ks[j][d], s);
        s *= 0.25f;                 // HEAD_D^-0.5 = 1/4
        S[i][j] = s;
        m = fmaxf(m, s);
    }

    // exp, denominator, weighted V accumulation
    float den = 0.f;
    float o[16] = {};
    #pragma unroll 4
    for (int j = 0; j < 64; j++) {
        float e = __expf(S[i][j] - m);
        den += e;
        #pragma unroll
        for (int d = 0; d < 16; d++) o[d] = fmaf(e, Vs[j][d], o[d]);
    }
    float inv = 1.f / den;
    #pragma unroll
    for (int d = 0; d < 16; d++) g_a[off + d] = o[d] * inv;
}

// ---------------------------------------------------------------------------
extern "C" void kernel_launch(void* const* d_in, const int* in_sizes, int n_in,
                              void* d_out, int out_size)
{
    const float* x     = (const float*)d_in[0];
    const float* pos   = (const float*)d_in[1];
    const float* Wq    = (const float*)d_in[2];
    const float* bq    = (const float*)d_in[3];
    const float* Wk    = (const float*)d_in[4];
    const float* bk    = (const float*)d_in[5];
    const float* Wv    = (const float*)d_in[6];
    const float* bv    = (const float*)d_in[7];
    const float* Wo    = (const float*)d_in[8];
    const float* bo    = (const float*)d_in[9];
    const float* rfreq = (const float*)d_in[10];
    // d_in[11] = src, d_in[12] = dst : fully-connected within graph -> implicit
    float* out = (float*)d_out;

    float *qp, *kp, *vp, *ap;
    cudaGetSymbolAddress((void**)&qp, g_q);
    cudaGetSymbolAddress((void**)&kp, g_k);
    cudaGetSymbolAddress((void**)&vp, g_v);
    cudaGetSymbolAddress((void**)&ap, g_a);

    // Fused Q,K,V projections: grid.x = 3 * (384/64) = 18 tiles
    dim3 qkv_grid(3 * (C / 64), NTOT / 64);   // (18, 32)
    gemm3_tf32_kernel<<<qkv_grid, 128>>>(x, Wq, Wk, Wv, bq, bk, bv,
                                         qp, kp, vp, C, C);

    // Attention with fused RoPE
    attn_kernel<<<dim3(GH, NGR), 64>>>(pos, rfreq);

    // Output projection
    dim3 o_grid(C / 64, NTOT / 64);           // (6, 32)
    gemm3_tf32_kernel<<<o_grid, 128>>>(ap, Wo, Wo, Wo, bo, bo, bo,
                                       out, out, out, C, C);
}

// round 4
// speedup vs baseline: 2.5776x; 1.9878x over previous
#include <cuda_runtime.h>
#include <cuda_bf16.h>
#include <mma.h>

using namespace nvcuda;

// Problem constants (fixed by the reference)
#define NTOT   2048          // nodes total (32 graphs * 64 nodes)
#define NGR    32            // graphs
#define NPG    64            // nodes per graph
#define C      384           // in/emb/out channels
#define G12    12            // tetra group size
#define HEFF   2             // heads per group
#define GH     24            // G12*HEFF
#define HD     16            // head dim

// Scratch (device globals — no allocation allowed)
__device__ float g_q[NTOT * C];
__device__ float g_k[NTOT * C];
__device__ float g_v[NTOT * C];
__device__ float g_a[NTOT * C];

// ---------------------------------------------------------------------------
// Tensor-core GEMM, bf16 2-way split (hi+mid, 3 products ~ fp32-ish accuracy):
//   C[M,N] = A[M,K] @ B[K,N] + bias
// 64x64 tile, BK=32, 128 threads = 4 warps, each warp a 32x32 quadrant
// (2x2 wmma 16x16x16 bf16 tiles). Up to 3 B/bias/out selected by blockIdx.x
// (fuses the Q,K,V projections in one launch).
// Dims are multiples of tile sizes (2048 x 384 x 384) -> no guards.
// ---------------------------------------------------------------------------
#define AST 40   // A smem row stride (elements): 80B, LDSM bank-conflict-free
#define BST 72   // B smem row stride (elements): 144B, LDSM bank-conflict-free

__global__ __launch_bounds__(128) void gemm3_bf16_kernel(
    const float* __restrict__ A,
    const float* __restrict__ B0, const float* __restrict__ B1, const float* __restrict__ B2,
    const float* __restrict__ bias0, const float* __restrict__ bias1, const float* __restrict__ bias2,
    float* __restrict__ O0, float* __restrict__ O1, float* __restrict__ O2,
    int K, int N)
{
    const int ntiles = N >> 6;
    const int which = blockIdx.x / ntiles;
    const int bc    = blockIdx.x % ntiles;
    const int br    = blockIdx.y;

    const float* B    = (which == 0) ? B0    : (which == 1) ? B1    : B2;
    const float* bias = (which == 0) ? bias0 : (which == 1) ? bias1 : bias2;
    float*       O    = (which == 0) ? O0    : (which == 1) ? O1    : O2;

    __shared__ __align__(128) __nv_bfloat16 Ash[64][AST];
    __shared__ __align__(128) __nv_bfloat16 Asm[64][AST];
    __shared__ __align__(128) __nv_bfloat16 Bsh[32][BST];
    __shared__ __align__(128) __nv_bfloat16 Bsm[32][BST];
    __shared__ float Cs[64][64];

    const int tid  = threadIdx.x;
    const int warp = tid >> 5;
    const int wr   = warp >> 1;       // warp row quadrant (0/1)
    const int wc   = warp & 1;        // warp col quadrant (0/1)

    wmma::fragment<wmma::accumulator, 16, 16, 16, float> acc[2][2];
    #pragma unroll
    for (int i = 0; i < 2; i++)
        #pragma unroll
        for (int j = 0; j < 2; j++)
            wmma::fill_fragment(acc[i][j], 0.0f);

    for (int kt = 0; kt < K; kt += 32) {
        // Load A tile 64x32 (float4: 8 per row, 8 threads/row group)
        #pragma unroll
        for (int l = 0; l < 4; l++) {
            int idx = tid + l * 128;            // 0..511 float4 slots
            int r = idx >> 3, c4 = idx & 7;     // r 0..63, c4 0..7
            float4 a4 = *reinterpret_cast<const float4*>(&A[(br * 64 + r) * K + kt + c4 * 4]);
            float av[4] = {a4.x, a4.y, a4.z, a4.w};
            #pragma unroll
            for (int e = 0; e < 4; e++) {
                float a = av[e];
                __nv_bfloat16 hi = __float2bfloat16(a);
                Ash[r][c4 * 4 + e] = hi;
                Asm[r][c4 * 4 + e] = __float2bfloat16(a - __bfloat162float(hi));
            }
        }
        // Load B tile 32x64 (float4: 16 per row)
        #pragma unroll
        for (int l = 0; l < 4; l++) {
            int idx = tid + l * 128;            // 0..511
            int r = idx >> 4, c4 = idx & 15;    // r 0..31, c4 0..15
            float4 b4 = *reinterpret_cast<const float4*>(&B[(kt + r) * N + bc * 64 + c4 * 4]);
            float bv[4] = {b4.x, b4.y, b4.z, b4.w};
            #pragma unroll
            for (int e = 0; e < 4; e++) {
                float b = bv[e];
                __nv_bfloat16 hi = __float2bfloat16(b);
                Bsh[r][c4 * 4 + e] = hi;
                Bsm[r][c4 * 4 + e] = __float2bfloat16(b - __bfloat162float(hi));
            }
        }
        __syncthreads();

        #pragma unroll
        for (int ks = 0; ks < 2; ks++) {
            wmma::fragment<wmma::matrix_a, 16, 16, 16, __nv_bfloat16, wmma::row_major> ah[2], am[2];
            wmma::fragment<wmma::matrix_b, 16, 16, 16, __nv_bfloat16, wmma::row_major> bh[2], bm[2];
            #pragma unroll
            for (int i = 0; i < 2; i++) {
                wmma::load_matrix_sync(ah[i], &Ash[wr * 32 + i * 16][ks * 16], AST);
                wmma::load_matrix_sync(am[i], &Asm[wr * 32 + i * 16][ks * 16], AST);
            }
            #pragma unroll
            for (int j = 0; j < 2; j++) {
                wmma::load_matrix_sync(bh[j], &Bsh[ks * 16][wc * 32 + j * 16], BST);
                wmma::load_matrix_sync(bm[j], &Bsm[ks * 16][wc * 32 + j * 16], BST);
            }
            #pragma unroll
            for (int i = 0; i < 2; i++)
                #pragma unroll
                for (int j = 0; j < 2; j++) {
                    wmma::mma_sync(acc[i][j], ah[i], bh[j], acc[i][j]);
                    wmma::mma_sync(acc[i][j], ah[i], bm[j], acc[i][j]);
                    wmma::mma_sync(acc[i][j], am[i], bh[j], acc[i][j]);
                }
        }
        __syncthreads();
    }

    // Epilogue: accumulators -> smem -> global (+bias), fully coalesced
    #pragma unroll
    for (int i = 0; i < 2; i++)
        #pragma unroll
        for (int j = 0; j < 2; j++)
            wmma::store_matrix_sync(&Cs[wr * 32 + i * 16][wc * 32 + j * 16],
                                    acc[i][j], 64, wmma::mem_row_major);
    __syncthreads();

    #pragma unroll
    for (int l = 0; l < 32; l++) {
        int idx = tid + l * 128;                // 0..4095
        int r = idx >> 6, c = idx & 63;
        O[(br * 64 + r) * N + bc * 64 + c] = Cs[r][c] + bias[bc * 64 + c];
    }
}

// ---------------------------------------------------------------------------
// Dense attention per (graph, group-head), RoPE fused into the load phase.
// 256 threads/block = 4 group-head slices of 64 threads (one query row each).
// No score matrix in smem: scores are recomputed in pass 2 (registers only).
// ---------------------------------------------------------------------------
__global__ __launch_bounds__(256) void attn_kernel(const float* __restrict__ pos,
                                                   const float* __restrict__ freqs)
{
    const int sub   = threadIdx.x >> 6;       // 0..3 group-head slice
    const int i     = threadIdx.x & 63;       // query/key row 0..63
    const int gh    = blockIdx.x * 4 + sub;   // 0..23
    const int graph = blockIdx.y;             // 0..31
    const int h     = gh & 1;                 // head-within-group

    __shared__ float Ks[4][64][16];
    __shared__ float Vs[4][64][16];

    const int node = graph * NPG + i;
    const int off  = node * C + gh * HD;

    // Load q,k rows into registers; v row into shared (float4 vectorized)
    float qr[16], kr[16];
    {
        const float4* qp = reinterpret_cast<const float4*>(g_q + off);
        const float4* kp = reinterpret_cast<const float4*>(g_k + off);
        const float4* vp = reinterpret_cast<const float4*>(g_v + off);
        float4* vs = reinterpret_cast<float4*>(&Vs[sub][i][0]);
        #pragma unroll
        for (int t = 0; t < 4; t++) {
            float4 qv = qp[t];
            qr[4*t+0] = qv.x; qr[4*t+1] = qv.y; qr[4*t+2] = qv.z; qr[4*t+3] = qv.w;
            float4 kv = kp[t];
            kr[4*t+0] = kv.x; kr[4*t+1] = kv.y; kr[4*t+2] = kv.z; kr[4*t+3] = kv.w;
            vs[t] = vp[t];
        }
    }

    // Fused RoPE: rotate (2f, 2f+1) pairs of q and k
    const float p0 = pos[node * 3 + 0];
    const float p1 = pos[node * 3 + 1];
    const float p2 = pos[node * 3 + 2];
    #pragma unroll
    for (int f = 0; f < 8; f++) {
        // freqs layout [3, HEFF, HD/2] = [3, 2, 8]
        float th = p0 * freqs[ 0 + h * 8 + f]
                 + p1 * freqs[16 + h * 8 + f]
                 + p2 * freqs[32 + h * 8 + f];
        float s, c;
        __sincosf(th, &s, &c);
        float q1 = qr[2*f], q2 = qr[2*f+1];
        qr[2*f]   = q1 * c - q2 * s;
        qr[2*f+1] = q1 * s + q2 * c;
        float k1 = kr[2*f], k2 = kr[2*f+1];
        kr[2*f]   = k1 * c - k2 * s;
        kr[2*f+1] = k1 * s + k2 * c;
    }
    #pragma unroll
    for (int d = 0; d < 16; d++) Ks[sub][i][d] = kr[d];
    __syncthreads();

    // Pass 1: max of scores (broadcast smem reads: whole warp same j,d)
    float m = -1e30f;
    #pragma unroll 4
    for (int j = 0; j < 64; j++) {
        float s = 0.f;
        #pragma unroll
        for (int d = 0; d < 16; d++) s = fmaf(qr[d], Ks[sub][j][d], s);
        m = fmaxf(m, s * 0.25f);      // HEAD_D^-0.5 = 1/4
    }

    // Pass 2: recompute scores, exp, denominator, weighted V accumulation
    float den = 0.f;
    float o[16] = {};
    #pragma unroll 2
    for (int j = 0; j < 64; j++) {
        float s = 0.f;
        #pragma unroll
        for (int d = 0; d < 16; d++) s = fmaf(qr[d], Ks[sub][j][d], s);
        float e = __expf(s * 0.25f - m);
        den += e;
        #pragma unroll
        for (int d = 0; d < 16; d++) o[d] = fmaf(e, Vs[sub][j][d], o[d]);
    }
    float inv = 1.f / den;
    #pragma unroll
    for (int d = 0; d < 16; d++) g_a[off + d] = o[d] * inv;
}

// ---------------------------------------------------------------------------
extern "C" void kernel_launch(void* const* d_in, const int* in_sizes, int n_in,
                              void* d_out, int out_size)
{
    const float* x     = (const float*)d_in[0];
    const float* pos   = (const float*)d_in[1];
    const float* Wq    = (const float*)d_in[2];
    const float* bq    = (const float*)d_in[3];
    const float* Wk    = (const float*)d_in[4];
    const float* bk    = (const float*)d_in[5];
    const float* Wv    = (const float*)d_in[6];
    const float* bv    = (const float*)d_in[7];
    const float* Wo    = (const float*)d_in[8];
    const float* bo    = (const float*)d_in[9];
    const float* rfreq = (const float*)d_in[10];
    // d_in[11] = src, d_in[12] = dst : fully-connected within graph -> implicit
    float* out = (float*)d_out;

    float *qp, *kp, *vp, *ap;
    cudaGetSymbolAddress((void**)&qp, g_q);
    cudaGetSymbolAddress((void**)&kp, g_k);
    cudaGetSymbolAddress((void**)&vp, g_v);
    cudaGetSymbolAddress((void**)&ap, g_a);

    // Fused Q,K,V projections: grid.x = 3 * (384/64) = 18 tiles
    dim3 qkv_grid(3 * (C / 64), NTOT / 64);   // (18, 32)
    gemm3_bf16_kernel<<<qkv_grid, 128>>>(x, Wq, Wk, Wv, bq, bk, bv,
                                         qp, kp, vp, C, C);

    // Attention with fused RoPE: 4 group-heads per 256-thread block
    attn_kernel<<<dim3(GH / 4, NGR), 256>>>(pos, rfreq);

    // Output projection
    dim3 o_grid(C / 64, NTOT / 64);           // (6, 32)
    gemm3_bf16_kernel<<<o_grid, 128>>>(ap, Wo, Wo, Wo, bo, bo, bo,
                                       out, out, out, C, C);
}

// round 5
// speedup vs baseline: 2.7251x; 1.0572x over previous
#include <cuda_runtime.h>
#include <cuda_bf16.h>
#include <mma.h>

using namespace nvcuda;

// Problem constants (fixed by the reference)
#define NTOT   2048          // nodes total (32 graphs * 64 nodes)
#define NGR    32            // graphs
#define NPG    64            // nodes per graph
#define C      384           // in/emb/out channels
#define G12    12            // tetra group size
#define HEFF   2             // heads per group
#define GH     24            // G12*HEFF
#define HD     16            // head dim

#define XN (NTOT * C)        // 786432
#define WN (C * C)           // 147456

// Scratch (device globals — no allocation allowed)
__device__ float g_q[XN];
__device__ float g_k[XN];
__device__ float g_v[XN];
// bf16 hi/mid splits
__device__ __nv_bfloat16 g_xh[XN];
__device__ __nv_bfloat16 g_xm[XN];
__device__ __nv_bfloat16 g_wh[4 * WN];   // Wq | Wk | Wv | Wo
__device__ __nv_bfloat16 g_wm[4 * WN];
__device__ __nv_bfloat16 g_ah[XN];       // attention output hi
__device__ __nv_bfloat16 g_am[XN];       // attention output mid

// ---------------------------------------------------------------------------
// One-shot split: x and the 4 weight matrices -> bf16 hi + mid.
// Index space: [0, XN) = x; then 4 blocks of WN for Wq,Wk,Wv,Wo.
// All boundaries are multiples of 1024 (256 threads * 4 elems). float4 loads.
// ---------------------------------------------------------------------------
__global__ __launch_bounds__(256) void split_kernel(
    const float* __restrict__ x,
    const float* __restrict__ wq, const float* __restrict__ wk,
    const float* __restrict__ wv, const float* __restrict__ wo,
    __nv_bfloat16* __restrict__ xh, __nv_bfloat16* __restrict__ xm,
    __nv_bfloat16* __restrict__ wh, __nv_bfloat16* __restrict__ wm)
{
    int idx = (blockIdx.x * 256 + threadIdx.x) * 4;
    const float* src;
    __nv_bfloat16 *dh, *dm;
    int loc;
    if (idx < XN) {
        src = x; dh = xh; dm = xm; loc = idx;
    } else {
        int w = idx - XN;
        int m = w / WN;
        loc = w - m * WN;
        src = (m == 0) ? wq : (m == 1) ? wk : (m == 2) ? wv : wo;
        dh = wh + m * WN; dm = wm + m * WN;
    }
    float4 v4 = *reinterpret_cast<const float4*>(&src[loc]);
    float v[4] = {v4.x, v4.y, v4.z, v4.w};
    __nv_bfloat16 h[4], m_[4];
    #pragma unroll
    for (int e = 0; e < 4; e++) {
        h[e]  = __float2bfloat16(v[e]);
        m_[e] = __float2bfloat16(v[e] - __bfloat162float(h[e]));
    }
    __nv_bfloat162 hp0(h[0], h[1]), hp1(h[2], h[3]);
    __nv_bfloat162 mp0(m_[0], m_[1]), mp1(m_[2], m_[3]);
    *reinterpret_cast<uint2*>(&dh[loc]) = make_uint2(
        *reinterpret_cast<unsigned*>(&hp0), *reinterpret_cast<unsigned*>(&hp1));
    *reinterpret_cast<uint2*>(&dm[loc]) = make_uint2(
        *reinterpret_cast<unsigned*>(&mp0), *reinterpret_cast<unsigned*>(&mp1));
}

// ---------------------------------------------------------------------------
// Tensor-core GEMM on pre-split bf16 (hi+mid, 3 products ~ fp32 accuracy):
//   O[M,N] = A[M,K] @ W[K,N] + bias  (fp32 out)
// 128x64 tile, BK=32, 256 threads = 8 warps (4 row x 2 col quadrants of 32x32),
// wmma 16x16x16. Up to 3 weight matrices selected by blockIdx.x (QKV fusion).
// Epilogue fp32 buffer aliases the tile smem (32KB total static smem).
// ---------------------------------------------------------------------------
#define AST 40   // A smem row stride (elements): 80B  -> LDSM conflict-free
#define BST 72   // B smem row stride (elements): 144B -> LDSM conflict-free
#define ASH_OFF 0
#define ASM_OFF (128 * AST * 2)                 // 10240
#define BSH_OFF (ASM_OFF + 128 * AST * 2)       // 20480
#define BSM_OFF (BSH_OFF + 32 * BST * 2)        // 25088
#define SMEM_BYTES (128 * 64 * 4)               // 32768 (Cs dominates)

__global__ __launch_bounds__(256) void gemm_bf16s_kernel(
    const __nv_bfloat16* __restrict__ Ah, const __nv_bfloat16* __restrict__ Am,
    const __nv_bfloat16* __restrict__ Wh, const __nv_bfloat16* __restrict__ Wm,
    const float* __restrict__ bias0, const float* __restrict__ bias1, const float* __restrict__ bias2,
    float* __restrict__ O0, float* __restrict__ O1, float* __restrict__ O2,
    int K, int N)
{
    const int ntiles = N >> 6;
    const int which = blockIdx.x / ntiles;
    const int bc    = blockIdx.x % ntiles;
    const int br    = blockIdx.y;

    const __nv_bfloat16* Bh = Wh + which * K * N;
    const __nv_bfloat16* Bm = Wm + which * K * N;
    const float* bias = (which == 0) ? bias0 : (which == 1) ? bias1 : bias2;
    float*       O    = (which == 0) ? O0    : (which == 1) ? O1    : O2;

    __shared__ __align__(16) unsigned char smem_raw[SMEM_BYTES];
    __nv_bfloat16 (*Ash)[AST] = reinterpret_cast<__nv_bfloat16(*)[AST]>(smem_raw + ASH_OFF);
    __nv_bfloat16 (*Asm)[AST] = reinterpret_cast<__nv_bfloat16(*)[AST]>(smem_raw + ASM_OFF);
    __nv_bfloat16 (*Bsh)[BST] = reinterpret_cast<__nv_bfloat16(*)[BST]>(smem_raw + BSH_OFF);
    __nv_bfloat16 (*Bsm)[BST] = reinterpret_cast<__nv_bfloat16(*)[BST]>(smem_raw + BSM_OFF);
    float (*Cs)[64] = reinterpret_cast<float(*)[64]>(smem_raw);

    const int tid  = threadIdx.x;
    const int warp = tid >> 5;
    const int wr   = warp >> 1;       // 0..3: 32-row band
    const int wc   = warp & 1;        // 0..1: 32-col band

    wmma::fragment<wmma::accumulator, 16, 16, 16, float> acc[2][2];
    #pragma unroll
    for (int i = 0; i < 2; i++)
        #pragma unroll
        for (int j = 0; j < 2; j++)
            wmma::fill_fragment(acc[i][j], 0.0f);

    for (int kt = 0; kt < K; kt += 32) {
        // A tile 128x32: 4 uint4 per row, 512 per split, 2 per thread
        #pragma unroll
        for (int l = 0; l < 2; l++) {
            int idx = tid + l * 256;
            int r = idx >> 2, c8 = idx & 3;
            long goff = (long)(br * 128 + r) * K + kt + c8 * 8;
            *reinterpret_cast<uint4*>(&Ash[r][c8 * 8]) =
                *reinterpret_cast<const uint4*>(&Ah[goff]);
            *reinterpret_cast<uint4*>(&Asm[r][c8 * 8]) =
                *reinterpret_cast<const uint4*>(&Am[goff]);
        }
        // B tile 32x64: 8 uint4 per row, 256 per split, 1 per thread
        {
            int r = tid >> 3, c8 = tid & 7;
            long goff = (long)(kt + r) * N + bc * 64 + c8 * 8;
            *reinterpret_cast<uint4*>(&Bsh[r][c8 * 8]) =
                *reinterpret_cast<const uint4*>(&Bh[goff]);
            *reinterpret_cast<uint4*>(&Bsm[r][c8 * 8]) =
                *reinterpret_cast<const uint4*>(&Bm[goff]);
        }
        __syncthreads();

        #pragma unroll
        for (int ks = 0; ks < 2; ks++) {
            wmma::fragment<wmma::matrix_a, 16, 16, 16, __nv_bfloat16, wmma::row_major> ah[2], am[2];
            wmma::fragment<wmma::matrix_b, 16, 16, 16, __nv_bfloat16, wmma::row_major> bh[2], bm[2];
            #pragma unroll
            for (int i = 0; i < 2; i++) {
                wmma::load_matrix_sync(ah[i], &Ash[wr * 32 + i * 16][ks * 16], AST);
                wmma::load_matrix_sync(am[i], &Asm[wr * 32 + i * 16][ks * 16], AST);
            }
            #pragma unroll
            for (int j = 0; j < 2; j++) {
                wmma::load_matrix_sync(bh[j], &Bsh[ks * 16][wc * 32 + j * 16], BST);
                wmma::load_matrix_sync(bm[j], &Bsm[ks * 16][wc * 32 + j * 16], BST);
            }
            #pragma unroll
            for (int i = 0; i < 2; i++)
                #pragma unroll
                for (int j = 0; j < 2; j++) {
                    wmma::mma_sync(acc[i][j], ah[i], bh[j], acc[i][j]);
                    wmma::mma_sync(acc[i][j], ah[i], bm[j], acc[i][j]);
                    wmma::mma_sync(acc[i][j], am[i], bh[j], acc[i][j]);
                }
        }
        __syncthreads();
    }

    // Epilogue: accumulators -> (aliased) smem -> global (+bias), coalesced
    #pragma unroll
    for (int i = 0; i < 2; i++)
        #pragma unroll
        for (int j = 0; j < 2; j++)
            wmma::store_matrix_sync(&Cs[wr * 32 + i * 16][wc * 32 + j * 16],
                                    acc[i][j], 64, wmma::mem_row_major);
    __syncthreads();

    #pragma unroll
    for (int l = 0; l < 32; l++) {
        int idx = tid + l * 256;                // 0..8191
        int r = idx >> 6, c = idx & 63;
        O[(long)(br * 128 + r) * N + bc * 64 + c] = Cs[r][c] + bias[bc * 64 + c];
    }
}

// ---------------------------------------------------------------------------
// Dense attention per (graph, group-head), RoPE fused into the load phase.
// 256 threads/block = 4 group-head slices of 64 threads (one query row each).
// Writes output directly as bf16 hi/mid splits (feeds the O-projection GEMM).
// ---------------------------------------------------------------------------
__global__ __launch_bounds__(256) void attn_kernel(const float* __restrict__ pos,
                                                   const float* __restrict__ freqs)
{
    const int sub   = threadIdx.x >> 6;       // 0..3 group-head slice
    const int i     = threadIdx.x & 63;       // query/key row 0..63
    const int gh    = blockIdx.x * 4 + sub;   // 0..23
    const int graph = blockIdx.y;             // 0..31
    const int h     = gh & 1;                 // head-within-group

    __shared__ float Ks[4][64][16];
    __shared__ float Vs[4][64][16];

    const int node = graph * NPG + i;
    const int off  = node * C + gh * HD;

    // Load q,k rows into registers; v row into shared (float4 vectorized)
    float qr[16], kr[16];
    {
        const float4* qp = reinterpret_cast<const float4*>(g_q + off);
        const float4* kp = reinterpret_cast<const float4*>(g_k + off);
        const float4* vp = reinterpret_cast<const float4*>(g_v + off);
        float4* vs = reinterpret_cast<float4*>(&Vs[sub][i][0]);
        #pragma unroll
        for (int t = 0; t < 4; t++) {
            float4 qv = qp[t];
            qr[4*t+0] = qv.x; qr[4*t+1] = qv.y; qr[4*t+2] = qv.z; qr[4*t+3] = qv.w;
            float4 kv = kp[t];
            kr[4*t+0] = kv.x; kr[4*t+1] = kv.y; kr[4*t+2] = kv.z; kr[4*t+3] = kv.w;
            vs[t] = vp[t];
        }
    }

    // Fused RoPE: rotate (2f, 2f+1) pairs of q and k
    const float p0 = pos[node * 3 + 0];
    const float p1 = pos[node * 3 + 1];
    const float p2 = pos[node * 3 + 2];
    #pragma unroll
    for (int f = 0; f < 8; f++) {
        // freqs layout [3, HEFF, HD/2] = [3, 2, 8]
        float th = p0 * freqs[ 0 + h * 8 + f]
                 + p1 * freqs[16 + h * 8 + f]
                 + p2 * freqs[32 + h * 8 + f];
        float s, c;
        __sincosf(th, &s, &c);
        float q1 = qr[2*f], q2 = qr[2*f+1];
        qr[2*f]   = q1 * c - q2 * s;
        qr[2*f+1] = q1 * s + q2 * c;
        float k1 = kr[2*f], k2 = kr[2*f+1];
        kr[2*f]   = k1 * c - k2 * s;
        kr[2*f+1] = k1 * s + k2 * c;
    }
    #pragma unroll
    for (int d = 0; d < 16; d++) Ks[sub][i][d] = kr[d];
    __syncthreads();

    // Pass 1: max of scores (broadcast smem reads: whole warp same j,d)
    float m = -1e30f;
    #pragma unroll 4
    for (int j = 0; j < 64; j++) {
        float s = 0.f;
        #pragma unroll
        for (int d = 0; d < 16; d++) s = fmaf(qr[d], Ks[sub][j][d], s);
        m = fmaxf(m, s * 0.25f);      // HEAD_D^-0.5 = 1/4
    }

    // Pass 2: recompute scores, exp, denominator, weighted V accumulation
    float den = 0.f;
    float o[16] = {};
    #pragma unroll 2
    for (int j = 0; j < 64; j++) {
        float s = 0.f;
        #pragma unroll
        for (int d = 0; d < 16; d++) s = fmaf(qr[d], Ks[sub][j][d], s);
        float e = __expf(s * 0.25f - m);
        den += e;
        #pragma unroll
        for (int d = 0; d < 16; d++) o[d] = fmaf(e, Vs[sub][j][d], o[d]);
    }
    float inv = 1.f / den;

    // Write bf16 hi/mid splits directly (vectorized 16B stores)
    __nv_bfloat16 hb[16], mb[16];
    #pragma unroll
    for (int d = 0; d < 16; d++) {
        float val = o[d] * inv;
        hb[d] = __float2bfloat16(val);
        mb[d] = __float2bfloat16(val - __bfloat162float(hb[d]));
    }
    uint4 uh0, uh1, um0, um1;
    unsigned* uhp0 = &uh0.x; unsigned* uhp1 = &uh1.x;
    unsigned* ump0 = &um0.x; unsigned* ump1 = &um1.x;
    #pragma unroll
    for (int t = 0; t < 4; t++) {
        __nv_bfloat162 a(hb[2*t], hb[2*t+1]);       uhp0[t] = *reinterpret_cast<unsigned*>(&a);
        __nv_bfloat162 b(hb[8+2*t], hb[8+2*t+1]);   uhp1[t] = *reinterpret_cast<unsigned*>(&b);
        __nv_bfloat162 c2(mb[2*t], mb[2*t+1]);      ump0[t] = *reinterpret_cast<unsigned*>(&c2);
        __nv_bfloat162 d2(mb[8+2*t], mb[8+2*t+1]);  ump1[t] = *reinterpret_cast<unsigned*>(&d2);
    }
    uint4* ah = reinterpret_cast<uint4*>(&g_ah[off]);
    uint4* am = reinterpret_cast<uint4*>(&g_am[off]);
    ah[0] = uh0; ah[1] = uh1;
    am[0] = um0; am[1] = um1;
}

// ---------------------------------------------------------------------------
extern "C" void kernel_launch(void* const* d_in, const int* in_sizes, int n_in,
                              void* d_out, int out_size)
{
    const float* x     = (const float*)d_in[0];
    const float* pos   = (const float*)d_in[1];
    const float* Wq    = (const float*)d_in[2];
    const float* bq    = (const float*)d_in[3];
    const float* Wk    = (const float*)d_in[4];
    const float* bk    = (const float*)d_in[5];
    const float* Wv    = (const float*)d_in[6];
    const float* bv    = (const float*)d_in[7];
    const float* Wo    = (const float*)d_in[8];
    const float* bo    = (const float*)d_in[9];
    const float* rfreq = (const float*)d_in[10];
    // d_in[11] = src, d_in[12] = dst : fully-connected within graph -> implicit
    float* out = (float*)d_out;

    float *qp, *kp, *vp;
    __nv_bfloat16 *xh, *xm, *wh, *wm, *ahp, *amp;
    cudaGetSymbolAddress((void**)&qp, g_q);
    cudaGetSymbolAddress((void**)&kp, g_k);
    cudaGetSymbolAddress((void**)&vp, g_v);
    cudaGetSymbolAddress((void**)&xh, g_xh);
    cudaGetSymbolAddress((void**)&xm, g_xm);
    cudaGetSymbolAddress((void**)&wh, g_wh);
    cudaGetSymbolAddress((void**)&wm, g_wm);
    cudaGetSymbolAddress((void**)&ahp, g_ah);
    cudaGetSymbolAddress((void**)&amp, g_am);

    // 1) Split x and weights into bf16 hi/mid (one-shot per launch)
    int total = XN + 4 * WN;                  // 1376256
    split_kernel<<<total / 1024, 256>>>(x, Wq, Wk, Wv, Wo, xh, xm, wh, wm);

    // 2) Fused Q,K,V projections: grid (3*6, 16)
    dim3 qkv_grid(3 * (C / 64), NTOT / 128);
    gemm_bf16s_kernel<<<qkv_grid, 256>>>(xh, xm, wh, wm,
                                         bq, bk, bv, qp, kp, vp, C, C);

    // 3) Attention with fused RoPE: 4 group-heads per 256-thread block
    attn_kernel<<<dim3(GH / 4, NGR), 256>>>(pos, rfreq);

    // 4) Output projection (weights at offset 3*WN)
    dim3 o_grid(C / 64, NTOT / 128);
    gemm_bf16s_kernel<<<o_grid, 256>>>(ahp, amp, wh + 3 * WN, wm + 3 * WN,
                                       bo, bo, bo, out, out, out, C, C);
}